// round 14
// baseline (speedup 1.0000x reference)
#include <cuda_runtime.h>
#include <cstdint>

#define T_STEPS 2048
#define BATCH   64
#define IN_DIM  128
#define HDIM    256
#define OUT_DIM 128
#define NTHR    512
#define NBLK    128           // 16 clusters of 8 CTAs; cluster = batch group
#define CLUSTER 8
#define WOPAD   264           // (8*o + k) mod 32 distinct -> conflict-free y weights
#define SENT    0x7fc0deadu   // NaN payload; h/x are always finite

// smem layout (floats)
#define OFF_ACT   0                       // [2][384][4] = 3072 (k<128 x | k>=128 h)
#define OFF_WOUT  3072                    // 16*264 = 4224
#define OFF_P     7296                    // [8][128][4] = 4096
#define OFF_G     11392                   // [128][4] = 512
#define OFF_BIAS  11904                   // 128
#define OFF_BOUT  12032                   // 16
#define SMEM_FLOATS 12048
#define SMEM_BYTES (SMEM_FLOATS * 4)      // 48192

__global__ void __launch_bounds__(NTHR, 1) __cluster_dims__(CLUSTER, 1, 1)
lstm_dsmem_sentinel_kernel(
    const float* __restrict__ input,   // [T, B, IN]
    const float* __restrict__ W_ih,    // [4H, IN]
    const float* __restrict__ W_hh,    // [4H, H]
    const float* __restrict__ b_ih,    // [4H]
    const float* __restrict__ b_hh,    // [4H]
    const float* __restrict__ W_out,   // [OUT, H]
    const float* __restrict__ b_out,   // [OUT]
    float* __restrict__ out,
    int out_size)
{
    extern __shared__ float sm[];
    float* sWo   = sm + OFF_WOUT;
    float* sP    = sm + OFF_P;
    float* sG    = sm + OFF_G;
    float* sBias = sm + OFF_BIAS;
    float* sBOut = sm + OFF_BOUT;

    const int tid = threadIdx.x;
    uint32_t rank;
    asm("mov.u32 %0, %%cluster_ctarank;" : "=r"(rank));
    const int grp   = blockIdx.x >> 3;      // batch group (4 rows)
    const int rbase = grp * 4;
    const int cb    = (int)rank * 32;       // h column base
    const uint32_t smB = (uint32_t)__cvta_generic_to_shared(sm);

    // ---- GEMM mapping (R13): col-pair m2 = tid&63, kq = tid>>6 (warp-uniform) ----
    const int m2 = tid & 63;
    const int kq = tid >> 6;
    const int c0 = 2 * m2, c1 = c0 + 1;
    const int grow0 = (c0 >> 5) * HDIM + cb + (c0 & 31);
    const int grow1 = grow0 + 1;

    // ---- weights in registers: 2 cols x (16 x-k + 32 h-k) = 96 regs ----
    float wx0[16], wx1[16], wh0[32], wh1[32];
    {
        const float* s0 = W_ih + (size_t)grow0 * IN_DIM + kq * 16;
        const float* s1 = W_ih + (size_t)grow1 * IN_DIM + kq * 16;
        #pragma unroll
        for (int i = 0; i < 16; i++) { wx0[i] = __ldg(s0 + i); wx1[i] = __ldg(s1 + i); }
        const float* h0 = W_hh + (size_t)grow0 * HDIM + kq * 32;
        const float* h1 = W_hh + (size_t)grow1 * HDIM + kq * 32;
        #pragma unroll
        for (int i = 0; i < 32; i++) { wh0[i] = __ldg(h0 + i); wh1[i] = __ldg(h1 + i); }
    }

    // ---- smem preload ----
    for (int i = tid; i < 16 * HDIM; i += NTHR) {
        int o = i >> 8, k = i & 255;
        sWo[o * WOPAD + k] = W_out[((int)rank * 16 + o) * HDIM + k];
    }
    if (tid < 128) {
        int gr = (tid >> 5) * HDIM + cb + (tid & 31);
        sBias[tid] = b_ih[gr] + b_hh[gr];
    }
    if (tid < 16) sBOut[tid] = b_out[(int)rank * 16 + tid];

    // ---- act init: zero both buffers; A[1] h-region = sentinel; x_0 -> A[0] ----
    for (int i = tid; i < 3072; i += NTHR) sm[i] = 0.0f;
    __syncthreads();
    if (tid < 128) {
        int r = tid >> 5, k5 = tid & 31;
        float4 v = *(const float4*)(input + ((size_t)rbase + r) * IN_DIM + k5 * 4);
        sm[(k5 * 4 + 0) * 4 + r] = v.x;
        sm[(k5 * 4 + 1) * 4 + r] = v.y;
        sm[(k5 * 4 + 2) * 4 + r] = v.z;
        sm[(k5 * 4 + 3) * 4 + r] = v.w;
    }
    {
        unsigned* h1r = (unsigned*)(sm + 1536 + 512);
        for (int i = tid; i < 1024; i += NTHR) h1r[i] = SENT;
    }
    __syncthreads();
    // peers must be initialized before any push can arrive
    asm volatile("barrier.cluster.arrive.aligned;" ::: "memory");
    asm volatile("barrier.cluster.wait.aligned;" ::: "memory");

    const size_t Y_TOTAL = (size_t)T_STEPS * BATCH * OUT_DIM;
    const bool write_tail = (out_size >= (int)(Y_TOTAL + 2 * BATCH * HDIM));

    float c_reg = 0.0f;   // cell state (r=tid>>5, c=tid&31), threads 0-127

    for (int t = 0; t < T_STEPS; t++) {
        const int buf  = t & 1;
        const int bufn = buf ^ 1;
        float* A  = sm + buf * 1536;
        float* An = sm + bufn * 1536;

        // ---- unified GEMM (x K=128 + h K=256), A[buf] fully resident ----
        unsigned long long a001 = 0ULL, a023 = 0ULL, a101 = 0ULL, a123 = 0ULL;
        {
            const ulonglong2* av = ((const ulonglong2*)A) + kq * 16;
            #pragma unroll
            for (int i = 0; i < 16; i++) {
                ulonglong2 p = av[i];
                unsigned long long wp0, wp1;
                unsigned u0 = __float_as_uint(wx0[i]), u1 = __float_as_uint(wx1[i]);
                asm("mov.b64 %0, {%1, %1};" : "=l"(wp0) : "r"(u0));
                asm("mov.b64 %0, {%1, %1};" : "=l"(wp1) : "r"(u1));
                asm("fma.rn.f32x2 %0, %1, %2, %0;" : "+l"(a001) : "l"(wp0), "l"(p.x));
                asm("fma.rn.f32x2 %0, %1, %2, %0;" : "+l"(a023) : "l"(wp0), "l"(p.y));
                asm("fma.rn.f32x2 %0, %1, %2, %0;" : "+l"(a101) : "l"(wp1), "l"(p.x));
                asm("fma.rn.f32x2 %0, %1, %2, %0;" : "+l"(a123) : "l"(wp1), "l"(p.y));
            }
            const ulonglong2* ah = ((const ulonglong2*)A) + 128 + kq * 32;
            #pragma unroll
            for (int i = 0; i < 32; i++) {
                ulonglong2 p = ah[i];
                unsigned long long wp0, wp1;
                unsigned u0 = __float_as_uint(wh0[i]), u1 = __float_as_uint(wh1[i]);
                asm("mov.b64 %0, {%1, %1};" : "=l"(wp0) : "r"(u0));
                asm("mov.b64 %0, {%1, %1};" : "=l"(wp1) : "r"(u1));
                asm("fma.rn.f32x2 %0, %1, %2, %0;" : "+l"(a001) : "l"(wp0), "l"(p.x));
                asm("fma.rn.f32x2 %0, %1, %2, %0;" : "+l"(a023) : "l"(wp0), "l"(p.y));
                asm("fma.rn.f32x2 %0, %1, %2, %0;" : "+l"(a101) : "l"(wp1), "l"(p.x));
                asm("fma.rn.f32x2 %0, %1, %2, %0;" : "+l"(a123) : "l"(wp1), "l"(p.y));
            }
            unsigned u0, u1, u2, u3;
            asm("mov.b64 {%0, %1}, %2;" : "=r"(u0), "=r"(u1) : "l"(a001));
            asm("mov.b64 {%0, %1}, %2;" : "=r"(u2), "=r"(u3) : "l"(a023));
            *(float4*)(sP + (kq * 128 + c0) * 4) =
                make_float4(__uint_as_float(u0), __uint_as_float(u1),
                            __uint_as_float(u2), __uint_as_float(u3));
            asm("mov.b64 {%0, %1}, %2;" : "=r"(u0), "=r"(u1) : "l"(a101));
            asm("mov.b64 {%0, %1}, %2;" : "=r"(u2), "=r"(u3) : "l"(a123));
            *(float4*)(sP + (kq * 128 + c1) * 4) =
                make_float4(__uint_as_float(u0), __uint_as_float(u1),
                            __uint_as_float(u2), __uint_as_float(u3));
        }
        __syncthreads();

        // ---- phase5: cell+push (w0-3) | x-pref (w4-7) | y+sentinel (w8-11) | spin (w12-15) ----
        if (tid < 128) {
            const float4* p4 = (const float4*)sP;
            float b = sBias[tid];
            float4 s = make_float4(b, b, b, b);
            #pragma unroll
            for (int q = 0; q < 8; q++) {
                float4 v = p4[q * 128 + tid];
                s.x += v.x; s.y += v.y; s.z += v.z; s.w += v.w;
            }
            *(float4*)(sG + tid * 4) = s;
            asm volatile("bar.sync 1, 128;" ::: "memory");

            const int r = tid >> 5, c = tid & 31;
            float gi = sG[(0 * 32 + c) * 4 + r];
            float gf = sG[(1 * 32 + c) * 4 + r];
            float gg = sG[(2 * 32 + c) * 4 + r];
            float go = sG[(3 * 32 + c) * 4 + r];
            float i_ = 1.0f / (1.0f + __expf(-gi));
            float f_ = 1.0f / (1.0f + __expf(-gf));
            float gv = tanhf(gg);
            float o_ = 1.0f / (1.0f + __expf(-go));
            float cn = f_ * c_reg + i_ * gv;
            float hn = o_ * tanhf(cn);
            c_reg = cn;

            // push h_{t+1}(r, cb+c) into all 8 peers' A[bufn] h-region
            {
                uint32_t loc = smB + (uint32_t)((bufn * 1536 + 512 + (cb + c) * 4 + r) * 4);
                #pragma unroll
                for (int p = 0; p < CLUSTER; p++) {
                    uint32_t ra;
                    asm("mapa.shared::cluster.u32 %0, %1, %2;" : "=r"(ra) : "r"(loc), "r"(p));
                    asm volatile("st.shared::cluster.f32 [%0], %1;"
                                 :: "r"(ra), "f"(hn) : "memory");
                }
            }
            if (t == T_STEPS - 1 && write_tail) {
                out[Y_TOTAL + (size_t)(rbase + r) * HDIM + cb + c] = hn;
                out[Y_TOTAL + BATCH * HDIM + (size_t)(rbase + r) * HDIM + cb + c] = cn;
            }
        } else if (tid < 256) {
            // x_{t+1} prefetch (transposed) into A[bufn] x-region
            if (t + 1 < T_STEPS) {
                int xr = (tid - 128) >> 5, xk5 = (tid - 128) & 31;
                float4 v = __ldcg((const float4*)(input
                        + ((size_t)(t + 1) * BATCH + rbase + xr) * IN_DIM + xk5 * 4));
                An[(xk5 * 4 + 0) * 4 + xr] = v.x;
                An[(xk5 * 4 + 1) * 4 + xr] = v.y;
                An[(xk5 * 4 + 2) * 4 + xr] = v.z;
                An[(xk5 * 4 + 3) * 4 + xr] = v.w;
            }
        } else if (tid < 384) {
            // y_{t-1} = h_t @ W_out^T (16 outs x 8 k-splits), then re-arm sentinel
            const int slot = tid - 256;
            if (t > 0) {
                const int o = slot >> 3, ks = slot & 7;
                float y0 = 0.f, y1 = 0.f, y2 = 0.f, y3 = 0.f;
                const float* wo = sWo + o * WOPAD + ks;
                const float4* ah = ((const float4*)A) + 128 + ks;
                #pragma unroll
                for (int i = 0; i < 32; i++) {
                    float w = wo[i * 8];
                    float4 h4 = ah[i * 8];
                    y0 += w * h4.x; y1 += w * h4.y; y2 += w * h4.z; y3 += w * h4.w;
                }
                #pragma unroll
                for (int s = 1; s <= 4; s <<= 1) {
                    y0 += __shfl_xor_sync(0xffffffffu, y0, s);
                    y1 += __shfl_xor_sync(0xffffffffu, y1, s);
                    y2 += __shfl_xor_sync(0xffffffffu, y2, s);
                    y3 += __shfl_xor_sync(0xffffffffu, y3, s);
                }
                if (ks == 0) {
                    float b = sBOut[o];
                    size_t yb = ((size_t)(t - 1) * BATCH + rbase) * OUT_DIM
                                + (size_t)rank * 16 + o;
                    out[yb + 0 * OUT_DIM] = y0 + b;
                    out[yb + 1 * OUT_DIM] = y1 + b;
                    out[yb + 2 * OUT_DIM] = y2 + b;
                    out[yb + 3 * OUT_DIM] = y3 + b;
                }
            }
            asm volatile("bar.sync 3, 128;" ::: "memory");   // y reads before sentinel
            {
                unsigned* d = (unsigned*)(A + 512) + slot * 8;
                #pragma unroll
                for (int j = 0; j < 8; j++) d[j] = SENT;
            }
        } else {
            // spin until all of A[bufn] h-region is pushed (value-based sync)
            const int idx = tid - 384;
            volatile unsigned* w = (volatile unsigned*)(An + 512) + idx * 8;
            #pragma unroll
            for (int j = 0; j < 8; j++) {
                while (w[j] == SENT) { }
            }
        }
        __syncthreads();
    }

    // ---- tail: y_{T-1} from h_T (A[0], fully spun-in last step) ----
    if (tid >= 256 && tid < 384) {
        const float* A = sm;   // buf 0
        const int slot = tid - 256;
        const int o = slot >> 3, ks = slot & 7;
        float y0 = 0.f, y1 = 0.f, y2 = 0.f, y3 = 0.f;
        const float* wo = sWo + o * WOPAD + ks;
        const float4* ah = ((const float4*)A) + 128 + ks;
        #pragma unroll
        for (int i = 0; i < 32; i++) {
            float w = wo[i * 8];
            float4 h4 = ah[i * 8];
            y0 += w * h4.x; y1 += w * h4.y; y2 += w * h4.z; y3 += w * h4.w;
        }
        #pragma unroll
        for (int s = 1; s <= 4; s <<= 1) {
            y0 += __shfl_xor_sync(0xffffffffu, y0, s);
            y1 += __shfl_xor_sync(0xffffffffu, y1, s);
            y2 += __shfl_xor_sync(0xffffffffu, y2, s);
            y3 += __shfl_xor_sync(0xffffffffu, y3, s);
        }
        if (ks == 0) {
            float b = sBOut[o];
            size_t yb = ((size_t)(T_STEPS - 1) * BATCH + rbase) * OUT_DIM
                        + (size_t)rank * 16 + o;
            out[yb + 0 * OUT_DIM] = y0 + b;
            out[yb + 1 * OUT_DIM] = y1 + b;
            out[yb + 2 * OUT_DIM] = y2 + b;
            out[yb + 3 * OUT_DIM] = y3 + b;
        }
    }
    // no CTA may exit while peers could still push into its smem
    asm volatile("barrier.cluster.arrive.aligned;" ::: "memory");
    asm volatile("barrier.cluster.wait.aligned;" ::: "memory");
}

extern "C" void kernel_launch(void* const* d_in, const int* in_sizes, int n_in,
                              void* d_out, int out_size) {
    const float* input = (const float*)d_in[0];
    const float* W_ih  = (const float*)d_in[1];
    const float* W_hh  = (const float*)d_in[2];
    const float* b_ih  = (const float*)d_in[3];
    const float* b_hh  = (const float*)d_in[4];
    const float* W_out = (const float*)d_in[5];
    const float* b_out = (const float*)d_in[6];
    float* out = (float*)d_out;
    (void)in_sizes; (void)n_in;

    cudaFuncSetAttribute(lstm_dsmem_sentinel_kernel,
                         cudaFuncAttributeMaxDynamicSharedMemorySize, SMEM_BYTES);
    lstm_dsmem_sentinel_kernel<<<NBLK, NTHR, SMEM_BYTES>>>(
        input, W_ih, W_hh, b_ih, b_hh, W_out, b_out, out, out_size);
}

// round 15
// speedup vs baseline: 2.1795x; 2.1795x over previous
#include <cuda_runtime.h>
#include <cstdint>

#define T_STEPS 2048
#define BATCH   64
#define IN_DIM  128
#define HDIM    256
#define OUT_DIM 128
#define NTHR    512
#define NBLK    128           // 16 groups (4 batch rows) x 8 ranks (32 h-cols)
#define WOPAD   272

// smem layout (floats)
#define OFF_ACT   0                       // [2][384][4]  = 3072
#define OFF_WOUT  3072                    // [16][272]    = 4352
#define OFF_P     7424                    // [8][128][4]  = 4096
#define OFF_G     11520                   // [128][4]     = 512
#define OFF_BIAS  12032                   // 128
#define OFF_BOUT  12160                   // 16
#define SMEM_FLOATS 12176
#define SMEM_BYTES (SMEM_FLOATS * 4)      // 48704

// persistent state: transposed h, double-buffered per group
__device__ float g_hT[16][2][HDIM * 4];   // [grp][buf][col*4 + r]
struct Flag { unsigned v; unsigned pad[31]; };
__device__ Flag g_flags[NBLK];            // counting flags: +128 per step

__device__ __forceinline__ unsigned ld_acq(const unsigned* p) {
    unsigned v;
    asm volatile("ld.acquire.gpu.global.u32 %0, [%1];" : "=r"(v) : "l"(p) : "memory");
    return v;
}
__device__ __forceinline__ void red_release_add(unsigned* p, unsigned v) {
    asm volatile("red.release.gpu.global.add.u32 [%0], %1;" :: "l"(p), "r"(v) : "memory");
}
__device__ __forceinline__ float sigm(float x) {
    return __fdividef(1.0f, 1.0f + __expf(-x));
}
__device__ __forceinline__ float tanh_fast(float x) {
    return __fdividef(2.0f, 1.0f + __expf(-2.0f * x)) - 1.0f;
}

__global__ void __launch_bounds__(NTHR, 1) lstm_red_kernel(
    const float* __restrict__ input,   // [T, B, IN]
    const float* __restrict__ W_ih,    // [4H, IN]
    const float* __restrict__ W_hh,    // [4H, H]
    const float* __restrict__ b_ih,    // [4H]
    const float* __restrict__ b_hh,    // [4H]
    const float* __restrict__ W_out,   // [OUT, H]
    const float* __restrict__ b_out,   // [OUT]
    float* __restrict__ out,
    int out_size)
{
    extern __shared__ float sm[];
    float* sAct  = sm + OFF_ACT;   // [buf][k][r]: k<128 x, k>=128 h
    float* sWo   = sm + OFF_WOUT;
    float* sP    = sm + OFF_P;     // split-K partials [8][128][4]
    float* sG    = sm + OFF_G;     // reduced gates [m][r]
    float* sBias = sm + OFF_BIAS;
    float* sBOut = sm + OFF_BOUT;

    const int tid  = threadIdx.x;
    const int bid  = blockIdx.x;
    const int grp  = bid >> 3;
    const int rank = bid & 7;
    const int rbase = grp * 4;
    const int cb    = rank * 32;

    const unsigned base = ld_acq(&g_flags[bid].v);   // counters uniform at start

    // ---- GEMM mapping (R13): col-pair m2 = tid&63 -> cols {2m2, 2m2+1};
    //      kq = tid>>6 (0..7) is warp-uniform -> activation LDS broadcasts ----
    const int m2 = tid & 63;
    const int kq = tid >> 6;
    const int c0 = 2 * m2, c1 = c0 + 1;
    const int grow0 = (c0 >> 5) * HDIM + cb + (c0 & 31);
    const int grow1 = grow0 + 1;

    // ---- weights in registers: 2 cols x (16 x-k + 32 h-k) = 96 regs ----
    float wx0[16], wx1[16], wh0[32], wh1[32];
    {
        const float* s0 = W_ih + (size_t)grow0 * IN_DIM + kq * 16;
        const float* s1 = W_ih + (size_t)grow1 * IN_DIM + kq * 16;
        #pragma unroll
        for (int i = 0; i < 16; i++) { wx0[i] = __ldg(s0 + i); wx1[i] = __ldg(s1 + i); }
        const float* h0 = W_hh + (size_t)grow0 * HDIM + kq * 32;
        const float* h1 = W_hh + (size_t)grow1 * HDIM + kq * 32;
        #pragma unroll
        for (int i = 0; i < 32; i++) { wh0[i] = __ldg(h0 + i); wh1[i] = __ldg(h1 + i); }
    }

    // ---- smem preload ----
    for (int i = tid; i < 16 * HDIM; i += NTHR) {
        int o = i >> 8, k = i & 255;
        sWo[o * WOPAD + k] = W_out[(rank * 16 + o) * HDIM + k];
    }
    if (tid < 128) {
        int gr = (tid >> 5) * HDIM + cb + (tid & 31);
        sBias[tid] = b_ih[gr] + b_hh[gr];
    }
    if (tid < 16) sBOut[tid] = b_out[rank * 16 + tid];

    // zero both act buffers (h_0 = 0), x_0 transposed into buf0
    for (int i = tid; i < 2 * 384 * 4; i += NTHR) sAct[i] = 0.0f;
    __syncthreads();
    if (tid < 128) {
        int r = tid >> 5, k5 = tid & 31;
        float4 v = *(const float4*)(input + ((size_t)rbase + r) * IN_DIM + k5 * 4);
        sAct[(k5 * 4 + 0) * 4 + r] = v.x;
        sAct[(k5 * 4 + 1) * 4 + r] = v.y;
        sAct[(k5 * 4 + 2) * 4 + r] = v.z;
        sAct[(k5 * 4 + 3) * 4 + r] = v.w;
    }
    __syncthreads();

    const size_t Y_TOTAL = (size_t)T_STEPS * BATCH * OUT_DIM;
    const bool write_tail = (out_size >= (int)(Y_TOTAL + 2 * BATCH * HDIM));

    float c_reg = 0.0f;   // cell state (r=tid>>5, c=tid&31), threads 0-127

    for (int t = 0; t < T_STEPS; t++) {
        const int buf = t & 1;
        float* A  = sAct + buf * 1536;
        float* An = sAct + (1 - buf) * 1536;

        // ---- phase 1: issue h_t fill LDGs; latency hides under x-GEMM ----
        float4 hv;
        if (tid < 256 && t > 0)
            hv = __ldcg(((const float4*)g_hT[grp][buf]) + tid);

        // ---- phase 2: x-part GEMM (K=128, 8-way split, 2 cols) ----
        unsigned long long a001 = 0ULL, a023 = 0ULL, a101 = 0ULL, a123 = 0ULL;
        {
            const ulonglong2* av = ((const ulonglong2*)A) + kq * 16;
            #pragma unroll
            for (int i = 0; i < 16; i++) {
                ulonglong2 p = av[i];
                unsigned long long wp0, wp1;
                unsigned u0 = __float_as_uint(wx0[i]), u1 = __float_as_uint(wx1[i]);
                asm("mov.b64 %0, {%1, %1};" : "=l"(wp0) : "r"(u0));
                asm("mov.b64 %0, {%1, %1};" : "=l"(wp1) : "r"(u1));
                asm("fma.rn.f32x2 %0, %1, %2, %0;" : "+l"(a001) : "l"(wp0), "l"(p.x));
                asm("fma.rn.f32x2 %0, %1, %2, %0;" : "+l"(a023) : "l"(wp0), "l"(p.y));
                asm("fma.rn.f32x2 %0, %1, %2, %0;" : "+l"(a101) : "l"(wp1), "l"(p.x));
                asm("fma.rn.f32x2 %0, %1, %2, %0;" : "+l"(a123) : "l"(wp1), "l"(p.y));
            }
        }

        // ---- phase 3: land the fill ----
        if (tid < 256 && t > 0)
            ((float4*)A)[128 + tid] = hv;
        __syncthreads();

        // ---- phase 4: h-part GEMM (K=256, 8-way split, 2 cols; critical) ----
        {
            const ulonglong2* av = ((const ulonglong2*)A) + 128 + kq * 32;
            #pragma unroll
            for (int i = 0; i < 32; i++) {
                ulonglong2 p = av[i];
                unsigned long long wp0, wp1;
                unsigned u0 = __float_as_uint(wh0[i]), u1 = __float_as_uint(wh1[i]);
                asm("mov.b64 %0, {%1, %1};" : "=l"(wp0) : "r"(u0));
                asm("mov.b64 %0, {%1, %1};" : "=l"(wp1) : "r"(u1));
                asm("fma.rn.f32x2 %0, %1, %2, %0;" : "+l"(a001) : "l"(wp0), "l"(p.x));
                asm("fma.rn.f32x2 %0, %1, %2, %0;" : "+l"(a023) : "l"(wp0), "l"(p.y));
                asm("fma.rn.f32x2 %0, %1, %2, %0;" : "+l"(a101) : "l"(wp1), "l"(p.x));
                asm("fma.rn.f32x2 %0, %1, %2, %0;" : "+l"(a123) : "l"(wp1), "l"(p.y));
            }
            unsigned u0, u1, u2, u3;
            asm("mov.b64 {%0, %1}, %2;" : "=r"(u0), "=r"(u1) : "l"(a001));
            asm("mov.b64 {%0, %1}, %2;" : "=r"(u2), "=r"(u3) : "l"(a023));
            *(float4*)(sP + (kq * 128 + c0) * 4) =
                make_float4(__uint_as_float(u0), __uint_as_float(u1),
                            __uint_as_float(u2), __uint_as_float(u3));
            asm("mov.b64 {%0, %1}, %2;" : "=r"(u0), "=r"(u1) : "l"(a101));
            asm("mov.b64 {%0, %1}, %2;" : "=r"(u2), "=r"(u3) : "l"(a123));
            *(float4*)(sP + (kq * 128 + c1) * 4) =
                make_float4(__uint_as_float(u0), __uint_as_float(u1),
                            __uint_as_float(u2), __uint_as_float(u3));
        }
        __syncthreads();

        const unsigned tgt = base + 128u * (unsigned)(t + 1);

        // ---- phase 5: reduce+cell+RED (w0-3) | x-pref+poll (w4-7) | y (w8-15) ----
        if (tid < 128) {
            const float4* p4 = (const float4*)sP;
            float b = sBias[tid];
            float4 s = make_float4(b, b, b, b);
            #pragma unroll
            for (int q = 0; q < 8; q++) {
                float4 v = p4[q * 128 + tid];
                s.x += v.x; s.y += v.y; s.z += v.z; s.w += v.w;
            }
            *(float4*)(sG + tid * 4) = s;
            asm volatile("bar.sync 1, 128;" ::: "memory");

            const int r = tid >> 5, c = tid & 31;
            float gi = sG[(0 * 32 + c) * 4 + r];
            float gf = sG[(1 * 32 + c) * 4 + r];
            float gg = sG[(2 * 32 + c) * 4 + r];
            float go = sG[(3 * 32 + c) * 4 + r];
            float i_ = sigm(gi);
            float f_ = sigm(gf);
            float gv = tanh_fast(gg);
            float o_ = sigm(go);
            float cn = f_ * c_reg + i_ * gv;
            float hn = o_ * tanh_fast(cn);
            c_reg = cn;

            __stcg(&g_hT[grp][1 - buf][(cb + c) * 4 + r], hn);

            if (t == T_STEPS - 1 && write_tail) {
                out[Y_TOTAL + (size_t)(rbase + r) * HDIM + cb + c] = hn;
                out[Y_TOTAL + BATCH * HDIM + (size_t)(rbase + r) * HDIM + cb + c] = cn;
            }
            // per-thread release: orders THIS thread's h store; counter hits
            // tgt only when all 128 cell threads have stored. No barrier.
            red_release_add(&g_flags[bid].v, 1u);
        } else if (tid < 256) {
            // x-prefetch (all 128); first 32 then poll (4 staggered per flag)
            if (t + 1 < T_STEPS) {
                int xr = (tid - 128) >> 5, xk5 = (tid - 128) & 31;
                float4 v = __ldcg((const float4*)(input
                        + ((size_t)(t + 1) * BATCH + rbase + xr) * IN_DIM + xk5 * 4));
                An[(xk5 * 4 + 0) * 4 + xr] = v.x;
                An[(xk5 * 4 + 1) * 4 + xr] = v.y;
                An[(xk5 * 4 + 2) * 4 + xr] = v.z;
                An[(xk5 * 4 + 3) * 4 + xr] = v.w;
            }
            if (tid < 160) {
                const unsigned* p = &g_flags[grp * 8 + ((tid - 128) & 7)].v;
                while (ld_acq(p) < tgt) { }
            }
        } else if (t > 0) {
            const int slot = tid - 256;
            const int o = slot >> 4, ks = slot & 15;
            float y0 = 0.f, y1 = 0.f, y2 = 0.f, y3 = 0.f;
            const float* wo = sWo + o * WOPAD + ks;
            const float4* ah = ((const float4*)A) + 128 + ks;
            #pragma unroll
            for (int i = 0; i < 16; i++) {
                float w = wo[i * 16];
                float4 h4 = ah[i * 16];
                y0 += w * h4.x; y1 += w * h4.y; y2 += w * h4.z; y3 += w * h4.w;
            }
            #pragma unroll
            for (int s = 1; s <= 8; s <<= 1) {
                y0 += __shfl_xor_sync(0xffffffffu, y0, s);
                y1 += __shfl_xor_sync(0xffffffffu, y1, s);
                y2 += __shfl_xor_sync(0xffffffffu, y2, s);
                y3 += __shfl_xor_sync(0xffffffffu, y3, s);
            }
            if (ks == 0) {
                float b = sBOut[o];
                size_t yb = ((size_t)(t - 1) * BATCH + rbase) * OUT_DIM
                            + (size_t)rank * 16 + o;
                out[yb + 0 * OUT_DIM] = y0 + b;
                out[yb + 1 * OUT_DIM] = y1 + b;
                out[yb + 2 * OUT_DIM] = y2 + b;
                out[yb + 3 * OUT_DIM] = y3 + b;
            }
        }
        __syncthreads();   // joins cell RED, pollers, prefetch, y-GEMM
    }

    // ---- tail: y_{T-1} from h_T (g_hT[grp][0]; final poll already passed) ----
    {
        float* A = sAct;   // buf 0
        if (tid < 256) {
            float4 v = __ldcg(((const float4*)g_hT[grp][0]) + tid);
            ((float4*)A)[128 + tid] = v;
        }
        __syncthreads();
        if (tid >= 256) {
            const int slot = tid - 256;
            const int o = slot >> 4, ks = slot & 15;
            float y0 = 0.f, y1 = 0.f, y2 = 0.f, y3 = 0.f;
            const float* wo = sWo + o * WOPAD + ks;
            const float4* ah = ((const float4*)A) + 128 + ks;
            #pragma unroll
            for (int i = 0; i < 16; i++) {
                float w = wo[i * 16];
                float4 h4 = ah[i * 16];
                y0 += w * h4.x; y1 += w * h4.y; y2 += w * h4.z; y3 += w * h4.w;
            }
            #pragma unroll
            for (int s = 1; s <= 8; s <<= 1) {
                y0 += __shfl_xor_sync(0xffffffffu, y0, s);
                y1 += __shfl_xor_sync(0xffffffffu, y1, s);
                y2 += __shfl_xor_sync(0xffffffffu, y2, s);
                y3 += __shfl_xor_sync(0xffffffffu, y3, s);
            }
            if (ks == 0) {
                float b = sBOut[o];
                size_t yb = ((size_t)(T_STEPS - 1) * BATCH + rbase) * OUT_DIM
                            + (size_t)rank * 16 + o;
                out[yb + 0 * OUT_DIM] = y0 + b;
                out[yb + 1 * OUT_DIM] = y1 + b;
                out[yb + 2 * OUT_DIM] = y2 + b;
                out[yb + 3 * OUT_DIM] = y3 + b;
            }
        }
    }
}

extern "C" void kernel_launch(void* const* d_in, const int* in_sizes, int n_in,
                              void* d_out, int out_size) {
    const float* input = (const float*)d_in[0];
    const float* W_ih  = (const float*)d_in[1];
    const float* W_hh  = (const float*)d_in[2];
    const float* b_ih  = (const float*)d_in[3];
    const float* b_hh  = (const float*)d_in[4];
    const float* W_out = (const float*)d_in[5];
    const float* b_out = (const float*)d_in[6];
    float* out = (float*)d_out;
    (void)in_sizes; (void)n_in;

    cudaFuncSetAttribute(lstm_red_kernel,
                         cudaFuncAttributeMaxDynamicSharedMemorySize, SMEM_BYTES);
    lstm_red_kernel<<<NBLK, NTHR, SMEM_BYTES>>>(
        input, W_ih, W_hh, b_ih, b_hh, W_out, b_out, out, out_size);
}

// round 16
// speedup vs baseline: 3.0110x; 1.3815x over previous
#include <cuda_runtime.h>
#include <cstdint>

#define T_STEPS 2048
#define BATCH   64
#define IN_DIM  128
#define HDIM    256
#define OUT_DIM 128
#define NTHR    512
#define NBLK    128           // 16 groups (4 batch rows) x 8 ranks (32 h-cols)
#define WOPAD   272

// smem layout (floats)
#define OFF_ACT   0                       // [2][384][4]  = 3072
#define OFF_WOUT  3072                    // [16][272]    = 4352
#define OFF_P     7424                    // [8][128][4]  = 4096
#define OFF_G     11520                   // [128][4]     = 512
#define OFF_BIAS  12032                   // 128
#define OFF_BOUT  12160                   // 16
#define SMEM_FLOATS 12176
#define SMEM_BYTES (SMEM_FLOATS * 4)      // 48704

// persistent exchange state: tagged h pairs {h, step-tag}, double-buffered.
// Tags are strictly monotonic across launches (epoch) -> no reset, replay-safe.
__device__ float2   g_hT[16][2][HDIM * 4];   // [grp][buf][col*4 + r] = {h, tag}
__device__ unsigned g_epoch[16];

__device__ __forceinline__ float sigm(float x) {
    return __fdividef(1.0f, 1.0f + __expf(-x));
}
__device__ __forceinline__ float tanh_fast(float x) {
    return __fdividef(2.0f, 1.0f + __expf(-2.0f * x)) - 1.0f;
}

__global__ void __launch_bounds__(NTHR, 1) lstm_tagged_kernel(
    const float* __restrict__ input,   // [T, B, IN]
    const float* __restrict__ W_ih,    // [4H, IN]
    const float* __restrict__ W_hh,    // [4H, H]
    const float* __restrict__ b_ih,    // [4H]
    const float* __restrict__ b_hh,    // [4H]
    const float* __restrict__ W_out,   // [OUT, H]
    const float* __restrict__ b_out,   // [OUT]
    float* __restrict__ out,
    int out_size)
{
    extern __shared__ float sm[];
    float* sAct  = sm + OFF_ACT;   // [buf][k][r]: k<128 x, k>=128 h
    float* sWo   = sm + OFF_WOUT;
    float* sP    = sm + OFF_P;     // split-K partials [8][128][4]
    float* sG    = sm + OFF_G;     // reduced gates [m][r]
    float* sBias = sm + OFF_BIAS;
    float* sBOut = sm + OFF_BOUT;

    const int tid  = threadIdx.x;
    const int bid  = blockIdx.x;
    const int grp  = bid >> 3;
    const int rank = bid & 7;
    const int rbase = grp * 4;
    const int cb    = rank * 32;

    const unsigned e = *((volatile unsigned*)&g_epoch[grp]);   // uniform in group

    // ---- GEMM mapping (R13): col-pair m2 = tid&63 -> cols {2m2, 2m2+1};
    //      kq = tid>>6 (0..7) is warp-uniform -> activation LDS broadcasts ----
    const int m2 = tid & 63;
    const int kq = tid >> 6;
    const int c0 = 2 * m2, c1 = c0 + 1;
    const int grow0 = (c0 >> 5) * HDIM + cb + (c0 & 31);
    const int grow1 = grow0 + 1;

    // ---- weights in registers: 2 cols x (16 x-k + 32 h-k) = 96 regs ----
    float wx0[16], wx1[16], wh0[32], wh1[32];
    {
        const float* s0 = W_ih + (size_t)grow0 * IN_DIM + kq * 16;
        const float* s1 = W_ih + (size_t)grow1 * IN_DIM + kq * 16;
        #pragma unroll
        for (int i = 0; i < 16; i++) { wx0[i] = __ldg(s0 + i); wx1[i] = __ldg(s1 + i); }
        const float* h0 = W_hh + (size_t)grow0 * HDIM + kq * 32;
        const float* h1 = W_hh + (size_t)grow1 * HDIM + kq * 32;
        #pragma unroll
        for (int i = 0; i < 32; i++) { wh0[i] = __ldg(h0 + i); wh1[i] = __ldg(h1 + i); }
    }

    // ---- smem preload ----
    for (int i = tid; i < 16 * HDIM; i += NTHR) {
        int o = i >> 8, k = i & 255;
        sWo[o * WOPAD + k] = W_out[(rank * 16 + o) * HDIM + k];
    }
    if (tid < 128) {
        int gr = (tid >> 5) * HDIM + cb + (tid & 31);
        sBias[tid] = b_ih[gr] + b_hh[gr];
    }
    if (tid < 16) sBOut[tid] = b_out[rank * 16 + tid];

    // zero both act buffers (h_0 = 0), x_0 transposed into buf0
    for (int i = tid; i < 2 * 384 * 4; i += NTHR) sAct[i] = 0.0f;
    __syncthreads();
    if (tid < 128) {
        int r = tid >> 5, k5 = tid & 31;
        float4 v = *(const float4*)(input + ((size_t)rbase + r) * IN_DIM + k5 * 4);
        sAct[(k5 * 4 + 0) * 4 + r] = v.x;
        sAct[(k5 * 4 + 1) * 4 + r] = v.y;
        sAct[(k5 * 4 + 2) * 4 + r] = v.z;
        sAct[(k5 * 4 + 3) * 4 + r] = v.w;
    }
    __syncthreads();

    const size_t Y_TOTAL = (size_t)T_STEPS * BATCH * OUT_DIM;
    const bool write_tail = (out_size >= (int)(Y_TOTAL + 2 * BATCH * HDIM));

    float c_reg = 0.0f;   // cell state (r=tid>>5, c=tid&31), threads 0-127

    for (int t = 0; t < T_STEPS; t++) {
        const int buf = t & 1;
        float* A  = sAct + buf * 1536;
        float* An = sAct + (1 - buf) * 1536;

        // ---- phase 1: speculative tagged-pair load (all 512 threads, 1 quad
        //      = 2 pairs each); detect is fused into the data load ----
        const float4* hsrc = ((const float4*)g_hT[grp][buf]) + tid;
        float4 v;
        if (t > 0) v = __ldcg(hsrc);

        // ---- phase 2: x-part GEMM (K=128, 8-way split, 2 cols) ----
        unsigned long long a001 = 0ULL, a023 = 0ULL, a101 = 0ULL, a123 = 0ULL;
        {
            const ulonglong2* av = ((const ulonglong2*)A) + kq * 16;
            #pragma unroll
            for (int i = 0; i < 16; i++) {
                ulonglong2 p = av[i];
                unsigned long long wp0, wp1;
                unsigned u0 = __float_as_uint(wx0[i]), u1 = __float_as_uint(wx1[i]);
                asm("mov.b64 %0, {%1, %1};" : "=l"(wp0) : "r"(u0));
                asm("mov.b64 %0, {%1, %1};" : "=l"(wp1) : "r"(u1));
                asm("fma.rn.f32x2 %0, %1, %2, %0;" : "+l"(a001) : "l"(wp0), "l"(p.x));
                asm("fma.rn.f32x2 %0, %1, %2, %0;" : "+l"(a023) : "l"(wp0), "l"(p.y));
                asm("fma.rn.f32x2 %0, %1, %2, %0;" : "+l"(a101) : "l"(wp1), "l"(p.x));
                asm("fma.rn.f32x2 %0, %1, %2, %0;" : "+l"(a123) : "l"(wp1), "l"(p.y));
            }
        }

        // ---- phase 3: tag-check (retry until fresh) and land the fill ----
        if (t > 0) {
            const unsigned want = e + (unsigned)t;   // tag of h_t
            while (__float_as_uint(v.y) != want || __float_as_uint(v.w) != want)
                v = __ldcg(hsrc);
            ((float2*)A)[256 + tid] = make_float2(v.x, v.z);
        }
        __syncthreads();

        // ---- phase 4: h-part GEMM (K=256, 8-way split, 2 cols; critical) ----
        {
            const ulonglong2* av = ((const ulonglong2*)A) + 128 + kq * 32;
            #pragma unroll
            for (int i = 0; i < 32; i++) {
                ulonglong2 p = av[i];
                unsigned long long wp0, wp1;
                unsigned u0 = __float_as_uint(wh0[i]), u1 = __float_as_uint(wh1[i]);
                asm("mov.b64 %0, {%1, %1};" : "=l"(wp0) : "r"(u0));
                asm("mov.b64 %0, {%1, %1};" : "=l"(wp1) : "r"(u1));
                asm("fma.rn.f32x2 %0, %1, %2, %0;" : "+l"(a001) : "l"(wp0), "l"(p.x));
                asm("fma.rn.f32x2 %0, %1, %2, %0;" : "+l"(a023) : "l"(wp0), "l"(p.y));
                asm("fma.rn.f32x2 %0, %1, %2, %0;" : "+l"(a101) : "l"(wp1), "l"(p.x));
                asm("fma.rn.f32x2 %0, %1, %2, %0;" : "+l"(a123) : "l"(wp1), "l"(p.y));
            }
            unsigned u0, u1, u2, u3;
            asm("mov.b64 {%0, %1}, %2;" : "=r"(u0), "=r"(u1) : "l"(a001));
            asm("mov.b64 {%0, %1}, %2;" : "=r"(u2), "=r"(u3) : "l"(a023));
            *(float4*)(sP + (kq * 128 + c0) * 4) =
                make_float4(__uint_as_float(u0), __uint_as_float(u1),
                            __uint_as_float(u2), __uint_as_float(u3));
            asm("mov.b64 {%0, %1}, %2;" : "=r"(u0), "=r"(u1) : "l"(a101));
            asm("mov.b64 {%0, %1}, %2;" : "=r"(u2), "=r"(u3) : "l"(a123));
            *(float4*)(sP + (kq * 128 + c1) * 4) =
                make_float4(__uint_as_float(u0), __uint_as_float(u1),
                            __uint_as_float(u2), __uint_as_float(u3));
        }
        __syncthreads();

        // ---- phase 5: reduce+cell+tagged store (w0-3) | x-pref (w4-7) | y (w8-15) ----
        if (tid < 128) {
            const float4* p4 = (const float4*)sP;
            float b = sBias[tid];
            float4 s = make_float4(b, b, b, b);
            #pragma unroll
            for (int q = 0; q < 8; q++) {
                float4 pv = p4[q * 128 + tid];
                s.x += pv.x; s.y += pv.y; s.z += pv.z; s.w += pv.w;
            }
            *(float4*)(sG + tid * 4) = s;
            asm volatile("bar.sync 1, 128;" ::: "memory");

            const int r = tid >> 5, c = tid & 31;
            float gi = sG[(0 * 32 + c) * 4 + r];
            float gf = sG[(1 * 32 + c) * 4 + r];
            float gg = sG[(2 * 32 + c) * 4 + r];
            float go = sG[(3 * 32 + c) * 4 + r];
            float i_ = sigm(gi);
            float f_ = sigm(gf);
            float gv = tanh_fast(gg);
            float o_ = sigm(go);
            float cn = f_ * c_reg + i_ * gv;
            float hn = o_ * tanh_fast(cn);
            c_reg = cn;

            // one stcg.64 carries value AND completion tag (per-element sync)
            float2 pr;
            pr.x = hn;
            pr.y = __uint_as_float(e + (unsigned)t + 1u);
            __stcg(&g_hT[grp][1 - buf][(cb + c) * 4 + r], pr);

            if (t == T_STEPS - 1 && write_tail) {
                out[Y_TOTAL + (size_t)(rbase + r) * HDIM + cb + c] = hn;
                out[Y_TOTAL + BATCH * HDIM + (size_t)(rbase + r) * HDIM + cb + c] = cn;
            }
        } else if (tid < 256) {
            // x_{t+1} prefetch (transposed) into A[next]
            if (t + 1 < T_STEPS) {
                int xr = (tid - 128) >> 5, xk5 = (tid - 128) & 31;
                float4 xv = __ldcg((const float4*)(input
                        + ((size_t)(t + 1) * BATCH + rbase + xr) * IN_DIM + xk5 * 4));
                An[(xk5 * 4 + 0) * 4 + xr] = xv.x;
                An[(xk5 * 4 + 1) * 4 + xr] = xv.y;
                An[(xk5 * 4 + 2) * 4 + xr] = xv.z;
                An[(xk5 * 4 + 3) * 4 + xr] = xv.w;
            }
        } else if (t > 0) {
            const int slot = tid - 256;
            const int o = slot >> 4, ks = slot & 15;
            float y0 = 0.f, y1 = 0.f, y2 = 0.f, y3 = 0.f;
            const float* wo = sWo + o * WOPAD + ks;
            const float4* ah = ((const float4*)A) + 128 + ks;
            #pragma unroll
            for (int i = 0; i < 16; i++) {
                float w = wo[i * 16];
                float4 h4 = ah[i * 16];
                y0 += w * h4.x; y1 += w * h4.y; y2 += w * h4.z; y3 += w * h4.w;
            }
            #pragma unroll
            for (int s = 1; s <= 8; s <<= 1) {
                y0 += __shfl_xor_sync(0xffffffffu, y0, s);
                y1 += __shfl_xor_sync(0xffffffffu, y1, s);
                y2 += __shfl_xor_sync(0xffffffffu, y2, s);
                y3 += __shfl_xor_sync(0xffffffffu, y3, s);
            }
            if (ks == 0) {
                float b = sBOut[o];
                size_t yb = ((size_t)(t - 1) * BATCH + rbase) * OUT_DIM
                            + (size_t)rank * 16 + o;
                out[yb + 0 * OUT_DIM] = y0 + b;
                out[yb + 1 * OUT_DIM] = y1 + b;
                out[yb + 2 * OUT_DIM] = y2 + b;
                out[yb + 3 * OUT_DIM] = y3 + b;
            }
        }
        __syncthreads();
    }

    // ---- tail: y_{T-1} from h_T (buf 0, tag e+T_STEPS) ----
    {
        float* A = sAct;   // buf 0
        const float4* hsrc = ((const float4*)g_hT[grp][0]) + tid;
        const unsigned want = e + (unsigned)T_STEPS;
        float4 v = __ldcg(hsrc);
        while (__float_as_uint(v.y) != want || __float_as_uint(v.w) != want)
            v = __ldcg(hsrc);
        ((float2*)A)[256 + tid] = make_float2(v.x, v.z);
        __syncthreads();
        if (tid >= 256) {
            const int slot = tid - 256;
            const int o = slot >> 4, ks = slot & 15;
            float y0 = 0.f, y1 = 0.f, y2 = 0.f, y3 = 0.f;
            const float* wo = sWo + o * WOPAD + ks;
            const float4* ah = ((const float4*)A) + 128 + ks;
            #pragma unroll
            for (int i = 0; i < 16; i++) {
                float w = wo[i * 16];
                float4 h4 = ah[i * 16];
                y0 += w * h4.x; y1 += w * h4.y; y2 += w * h4.z; y3 += w * h4.w;
            }
            #pragma unroll
            for (int s = 1; s <= 8; s <<= 1) {
                y0 += __shfl_xor_sync(0xffffffffu, y0, s);
                y1 += __shfl_xor_sync(0xffffffffu, y1, s);
                y2 += __shfl_xor_sync(0xffffffffu, y2, s);
                y3 += __shfl_xor_sync(0xffffffffu, y3, s);
            }
            if (ks == 0) {
                float b = sBOut[o];
                size_t yb = ((size_t)(T_STEPS - 1) * BATCH + rbase) * OUT_DIM
                            + (size_t)rank * 16 + o;
                out[yb + 0 * OUT_DIM] = y0 + b;
                out[yb + 1 * OUT_DIM] = y1 + b;
                out[yb + 2 * OUT_DIM] = y2 + b;
                out[yb + 3 * OUT_DIM] = y3 + b;
            }
        }
        __syncthreads();
        // advance epoch for the next launch/replay (tags stay monotonic)
        if (rank == 0 && tid == 0)
            *((volatile unsigned*)&g_epoch[grp]) = e + (unsigned)T_STEPS;
    }
}

extern "C" void kernel_launch(void* const* d_in, const int* in_sizes, int n_in,
                              void* d_out, int out_size) {
    const float* input = (const float*)d_in[0];
    const float* W_ih  = (const float*)d_in[1];
    const float* W_hh  = (const float*)d_in[2];
    const float* b_ih  = (const float*)d_in[3];
    const float* b_hh  = (const float*)d_in[4];
    const float* W_out = (const float*)d_in[5];
    const float* b_out = (const float*)d_in[6];
    float* out = (float*)d_out;
    (void)in_sizes; (void)n_in;

    cudaFuncSetAttribute(lstm_tagged_kernel,
                         cudaFuncAttributeMaxDynamicSharedMemorySize, SMEM_BYTES);
    lstm_tagged_kernel<<<NBLK, NTHR, SMEM_BYTES>>>(
        input, W_ih, W_hh, b_ih, b_hh, W_out, b_out, out, out_size);
}